// round 6
// baseline (speedup 1.0000x reference)
#include <cuda_runtime.h>
#include <math.h>

#define NN 50000
#define D 128
#define EMAX 800000
#define TILE 1024
#define NPART ((NN + TILE - 1) / TILE)   // 49

// GEMM dynamic smem: A tile 64x132 + full W 128x128
#define AS_ELEMS (64 * 132)
#define GEMM_SMEM ((AS_ELEMS + 128 * 128) * 4)

// ---- device scratch (no allocations allowed) ----
__device__ float g_g[(size_t)NN * D];
__device__ float g_act[(size_t)NN * D];
__device__ float g_dinv1[NN];
__device__ float g_dinv2[NN];
__device__ int   g_cnt1[NN];
__device__ int   g_cnt2[NN];
__device__ int   g_rowptr1[NN + 1];
__device__ int   g_rowptr2[NN + 1];
__device__ int   g_cursor1[NN];
__device__ int   g_cursor2[NN];
__device__ int   g_col1[EMAX];
__device__ int   g_col2[EMAX];
__device__ int   g_part1[NPART];
__device__ int   g_part2[NPART];

// ---- packed f32x2 helpers (sm_103a) ----
__device__ __forceinline__ unsigned long long pack2(float a) {
    unsigned long long r;
    asm("mov.b64 %0, {%1, %1};" : "=l"(r) : "f"(a));
    return r;
}
__device__ __forceinline__ void fma2(unsigned long long& d,
                                     unsigned long long a, unsigned long long b) {
    asm("fma.rn.f32x2 %0, %1, %2, %0;" : "+l"(d) : "l"(a), "l"(b));
}
__device__ __forceinline__ unsigned long long mul2(unsigned long long a,
                                                   unsigned long long b) {
    unsigned long long d;
    asm("mul.rn.f32x2 %0, %1, %2;" : "=l"(d) : "l"(a), "l"(b));
    return d;
}

// ---------------------------------------------------------------------------
__global__ void zero_both_kernel(int* __restrict__ c1, int* __restrict__ c2) {
    int i = blockIdx.x * blockDim.x + threadIdx.x;
    if (i < NN) c1[i] = 0;
    else if (i < 2 * NN) c2[i - NN] = 0;
}

// 2 edges per thread via int2.
__global__ void count_both_kernel(const int* __restrict__ ei1, int E1,
                                  const int* __restrict__ ei2, int E2,
                                  int* __restrict__ c1, int* __restrict__ c2) {
    int h1 = E1 >> 1, h2 = E2 >> 1;
    int i = blockIdx.x * blockDim.x + threadIdx.x;
    if (i < h1) {
        int2 d = reinterpret_cast<const int2*>(ei1 + E1)[i];
        atomicAdd(&c1[d.x], 1);
        atomicAdd(&c1[d.y], 1);
    } else if (i < h1 + h2) {
        int2 d = reinterpret_cast<const int2*>(ei2 + E2)[i - h1];
        atomicAdd(&c2[d.x], 1);
        atomicAdd(&c2[d.y], 1);
    } else {
        int k = i - h1 - h2;       // odd-E remainders
        if (k == 0 && (E1 & 1)) atomicAdd(&c1[ei1[E1 + E1 - 1]], 1);
        if (k == 1 && (E2 & 1)) atomicAdd(&c2[ei2[E2 + E2 - 1]], 1);
    }
}

// Phase A: per-tile partial sums (1024 elements/block) + fused dinv.
__global__ __launch_bounds__(256) void partial_dinv_kernel(
    const int* __restrict__ c1, float* __restrict__ d1, int* __restrict__ p1,
    const int* __restrict__ c2, float* __restrict__ d2, int* __restrict__ p2)
{
    int set = (blockIdx.x >= NPART) ? 1 : 0;
    int b = blockIdx.x - set * NPART;
    const int* c = set ? c2 : c1;
    float* dv    = set ? d2 : d1;
    int* part    = set ? p2 : p1;

    __shared__ int wsum[8];
    int tid = threadIdx.x;
    int base = b * TILE + tid * 4;
    int s = 0;
    #pragma unroll
    for (int k = 0; k < 4; k++) {
        int i = base + k;
        if (i < NN) {
            int v = c[i];
            s += v;
            dv[i] = rsqrtf((float)v + 1.0f);
        }
    }
    #pragma unroll
    for (int off = 16; off > 0; off >>= 1)
        s += __shfl_down_sync(0xFFFFFFFFu, s, off);
    if ((tid & 31) == 0) wsum[tid >> 5] = s;
    __syncthreads();
    if (tid < 8) {
        int t = wsum[tid];
        #pragma unroll
        for (int off = 4; off > 0; off >>= 1)
            t += __shfl_down_sync(0xFFu, t, off);
        if (tid == 0) part[b] = t;
    }
}

// Phase B: exclusive scan of NPART partials per set (2 blocks, 64 threads).
__global__ __launch_bounds__(64) void scan_partials_kernel(
    int* __restrict__ p1, int* __restrict__ rp1,
    int* __restrict__ p2, int* __restrict__ rp2)
{
    int* part = blockIdx.x ? p2 : p1;
    int* rp   = blockIdx.x ? rp2 : rp1;
    __shared__ int w0_total;
    int tid = threadIdx.x;
    int lane = tid & 31;
    int wid = tid >> 5;
    int v = (tid < NPART) ? part[tid] : 0;
    int incl = v;
    #pragma unroll
    for (int off = 1; off < 32; off <<= 1) {
        int t = __shfl_up_sync(0xFFFFFFFFu, incl, off);
        if (lane >= off) incl += t;
    }
    if (tid == 31) w0_total = incl;
    __syncthreads();
    if (wid == 1) incl += w0_total;
    if (tid < NPART) part[tid] = incl - v;
    if (tid == NPART - 1) rp[NN] = incl;
}

// Phase C: per-tile scan + offset, writes row_ptr and cursor.
__global__ __launch_bounds__(1024) void scan_tiles_kernel(
    const int* __restrict__ c1, int* __restrict__ rp1, int* __restrict__ cur1,
    const int* __restrict__ p1,
    const int* __restrict__ c2, int* __restrict__ rp2, int* __restrict__ cur2,
    const int* __restrict__ p2)
{
    int set = (blockIdx.x >= NPART) ? 1 : 0;
    int b = blockIdx.x - set * NPART;
    const int* cnt  = set ? c2 : c1;
    int* rp         = set ? rp2 : rp1;
    int* cur        = set ? cur2 : cur1;
    const int* part = set ? p2 : p1;

    __shared__ int warp_sums[32];
    int tid = threadIdx.x;
    int lane = tid & 31;
    int wid = tid >> 5;
    int i = b * TILE + tid;
    int v = (i < NN) ? cnt[i] : 0;
    int incl = v;
    #pragma unroll
    for (int off = 1; off < 32; off <<= 1) {
        int t = __shfl_up_sync(0xFFFFFFFFu, incl, off);
        if (lane >= off) incl += t;
    }
    if (lane == 31) warp_sums[wid] = incl;
    __syncthreads();
    if (wid == 0) {
        int s = warp_sums[lane];
        #pragma unroll
        for (int off = 1; off < 32; off <<= 1) {
            int t = __shfl_up_sync(0xFFFFFFFFu, s, off);
            if (lane >= off) s += t;
        }
        warp_sums[lane] = s;
    }
    __syncthreads();
    int woff = (wid > 0) ? warp_sums[wid - 1] : 0;
    int excl = incl - v + woff + part[b];
    if (i < NN) { rp[i] = excl; cur[i] = excl; }
}

// 2 edges per thread via int2.
__global__ void fill_both_kernel(const int* __restrict__ ei1, int E1,
                                 int* __restrict__ cur1, int* __restrict__ col1,
                                 const int* __restrict__ ei2, int E2,
                                 int* __restrict__ cur2, int* __restrict__ col2)
{
    int h1 = E1 >> 1, h2 = E2 >> 1;
    int i = blockIdx.x * blockDim.x + threadIdx.x;
    if (i < h1) {
        int2 s = reinterpret_cast<const int2*>(ei1)[i];
        int2 d = reinterpret_cast<const int2*>(ei1 + E1)[i];
        col1[atomicAdd(&cur1[d.x], 1)] = s.x;
        col1[atomicAdd(&cur1[d.y], 1)] = s.y;
    } else if (i < h1 + h2) {
        int2 s = reinterpret_cast<const int2*>(ei2)[i - h1];
        int2 d = reinterpret_cast<const int2*>(ei2 + E2)[i - h1];
        col2[atomicAdd(&cur2[d.x], 1)] = s.x;
        col2[atomicAdd(&cur2[d.y], 1)] = s.y;
    } else {
        int k = i - h1 - h2;
        if (k == 0 && (E1 & 1))
            col1[atomicAdd(&cur1[ei1[E1 + E1 - 1]], 1)] = ei1[E1 - 1];
        if (k == 1 && (E2 & 1))
            col2[atomicAdd(&cur2[ei2[E2 + E2 - 1]], 1)] = ei2[E2 - 1];
    }
}

// ---------------------------------------------------------------------------
// GEMM: g[row, col] = (sum_k A[row,k] * W[k,col]) * dinv[row].
// 64x128 block tile, 128 threads, 8x8 outputs per thread (f32x2 packed).
// Full W in smem; NO barriers in the k-loop.
__global__ __launch_bounds__(128) void gemm_scale_kernel(
    const float* __restrict__ A, const float* __restrict__ W,
    const float* __restrict__ dinv, float* __restrict__ g, int nrows)
{
    extern __shared__ float sm[];
    float* As = sm;                 // [64][132]
    float* Ws = sm + AS_ELEMS;      // [128][128]

    const int tid = threadIdx.x;
    const int row_base = blockIdx.x * 64;

    // Stage A tile (64x128, padded rows of 132)
    #pragma unroll
    for (int i = tid; i < 64 * 32; i += 128) {
        int r = i >> 5, c4 = i & 31;
        float4 v = make_float4(0.f, 0.f, 0.f, 0.f);
        if (row_base + r < nrows)
            v = reinterpret_cast<const float4*>(A)[(long)(row_base + r) * 32 + c4];
        *reinterpret_cast<float4*>(&As[r * 132 + c4 * 4]) = v;
    }
    // Stage full W (128x128)
    #pragma unroll
    for (int i = tid; i < 128 * 32; i += 128) {
        reinterpret_cast<float4*>(Ws)[i] = reinterpret_cast<const float4*>(W)[i];
    }
    __syncthreads();

    const int tx = tid & 15;
    const int ty = tid >> 4;
    const int col0 = tx * 8;
    const int row0 = ty * 8;

    unsigned long long acc2[8][4];
    #pragma unroll
    for (int r = 0; r < 8; r++)
        #pragma unroll
        for (int c = 0; c < 4; c++) acc2[r][c] = 0ull;

    #pragma unroll 4
    for (int kk4 = 0; kk4 < D; kk4 += 4) {
        float4 av[8];
        #pragma unroll
        for (int r = 0; r < 8; r++)
            av[r] = *reinterpret_cast<const float4*>(&As[(row0 + r) * 132 + kk4]);

        #pragma unroll
        for (int j = 0; j < 4; j++) {
            union { float4 f; unsigned long long u[2]; } w0, w1;
            w0.f = *reinterpret_cast<const float4*>(&Ws[(kk4 + j) * 128 + col0]);
            w1.f = *reinterpret_cast<const float4*>(&Ws[(kk4 + j) * 128 + col0 + 4]);
            unsigned long long wv[4] = { w0.u[0], w0.u[1], w1.u[0], w1.u[1] };
            const float* avf = reinterpret_cast<const float*>(av);
            #pragma unroll
            for (int r = 0; r < 8; r++) {
                unsigned long long aa = pack2(avf[r * 4 + j]);
                fma2(acc2[r][0], aa, wv[0]);
                fma2(acc2[r][1], aa, wv[1]);
                fma2(acc2[r][2], aa, wv[2]);
                fma2(acc2[r][3], aa, wv[3]);
            }
        }
    }

    #pragma unroll
    for (int r = 0; r < 8; r++) {
        int row = row_base + row0 + r;
        if (row >= nrows) continue;
        unsigned long long dd = pack2(dinv[row]);
        union { float4 f; unsigned long long u[2]; } o0, o1;
        o0.u[0] = mul2(acc2[r][0], dd);
        o0.u[1] = mul2(acc2[r][1], dd);
        o1.u[0] = mul2(acc2[r][2], dd);
        o1.u[1] = mul2(acc2[r][3], dd);
        long base = (long)row * 32 + (col0 >> 2);
        reinterpret_cast<float4*>(g)[base]     = o0.f;
        reinterpret_cast<float4*>(g)[base + 1] = o1.f;
    }
}

// ---------------------------------------------------------------------------
// Gather + finalize: one warp per node, 4-way unrolled for MLP.
__global__ __launch_bounds__(256) void gather_finalize_kernel(
    const float4* __restrict__ g, const int* __restrict__ row_ptr,
    const int* __restrict__ col, const float* __restrict__ dinv,
    const float4* __restrict__ b, float4* __restrict__ out, int relu_mode)
{
    int warp = (blockIdx.x * blockDim.x + threadIdx.x) >> 5;
    int lane = threadIdx.x & 31;
    if (warp >= NN) return;

    long base = (long)warp * 32 + lane;
    float4 a0 = g[base];
    float4 a1 = make_float4(0.f, 0.f, 0.f, 0.f);
    float4 a2 = make_float4(0.f, 0.f, 0.f, 0.f);
    float4 a3 = make_float4(0.f, 0.f, 0.f, 0.f);

    int jb = __ldg(&row_ptr[warp]);
    int je = __ldg(&row_ptr[warp + 1]);
    int j = jb;
    for (; j + 3 < je; j += 4) {
        int s0 = __ldg(&col[j]);
        int s1 = __ldg(&col[j + 1]);
        int s2 = __ldg(&col[j + 2]);
        int s3 = __ldg(&col[j + 3]);
        float4 v0 = g[(long)s0 * 32 + lane];
        float4 v1 = g[(long)s1 * 32 + lane];
        float4 v2 = g[(long)s2 * 32 + lane];
        float4 v3 = g[(long)s3 * 32 + lane];
        a0.x += v0.x; a0.y += v0.y; a0.z += v0.z; a0.w += v0.w;
        a1.x += v1.x; a1.y += v1.y; a1.z += v1.z; a1.w += v1.w;
        a2.x += v2.x; a2.y += v2.y; a2.z += v2.z; a2.w += v2.w;
        a3.x += v3.x; a3.y += v3.y; a3.z += v3.z; a3.w += v3.w;
    }
    for (; j < je; j++) {
        int s = __ldg(&col[j]);
        float4 v = g[(long)s * 32 + lane];
        a0.x += v.x; a0.y += v.y; a0.z += v.z; a0.w += v.w;
    }
    a0.x += a1.x + a2.x + a3.x;
    a0.y += a1.y + a2.y + a3.y;
    a0.z += a1.z + a2.z + a3.z;
    a0.w += a1.w + a2.w + a3.w;

    float dv = dinv[warp];
    float4 bb = b[lane];
    float o[4] = { fmaf(a0.x, dv, bb.x), fmaf(a0.y, dv, bb.y),
                   fmaf(a0.z, dv, bb.z), fmaf(a0.w, dv, bb.w) };
    if (relu_mode) {
        #pragma unroll
        for (int k = 0; k < 4; k++) o[k] = fmaxf(o[k], 0.0f);
    } else {
        #pragma unroll
        for (int k = 0; k < 4; k++) o[k] = (o[k] > 0.0f) ? o[k] : expm1f(o[k]);
    }
    out[base] = make_float4(o[0], o[1], o[2], o[3]);
}

// ---------------------------------------------------------------------------
extern "C" void kernel_launch(void* const* d_in, const int* in_sizes, int n_in,
                              void* d_out, int out_size)
{
    const float* x  = (const float*)d_in[0];
    const float* W1 = (const float*)d_in[1]; const float* b1 = (const float*)d_in[2];
    const float* W2 = (const float*)d_in[3]; const float* b2 = (const float*)d_in[4];
    const float* W3 = (const float*)d_in[5]; const float* b3 = (const float*)d_in[6];
    const float* W4 = (const float*)d_in[7]; const float* b4 = (const float*)d_in[8];
    const int* ei1 = (const int*)d_in[9];
    const int* ei2 = (const int*)d_in[10];
    const int E1 = in_sizes[9] / 2;
    const int E2 = in_sizes[10] / 2;

    float *gp, *actp, *dinv1, *dinv2;
    int *cnt1, *cnt2, *rp1, *rp2, *cur1, *cur2, *col1, *col2, *p1, *p2;
    cudaGetSymbolAddress((void**)&gp,   g_g);
    cudaGetSymbolAddress((void**)&actp, g_act);
    cudaGetSymbolAddress((void**)&dinv1, g_dinv1);
    cudaGetSymbolAddress((void**)&dinv2, g_dinv2);
    cudaGetSymbolAddress((void**)&cnt1, g_cnt1);
    cudaGetSymbolAddress((void**)&cnt2, g_cnt2);
    cudaGetSymbolAddress((void**)&rp1,  g_rowptr1);
    cudaGetSymbolAddress((void**)&rp2,  g_rowptr2);
    cudaGetSymbolAddress((void**)&cur1, g_cursor1);
    cudaGetSymbolAddress((void**)&cur2, g_cursor2);
    cudaGetSymbolAddress((void**)&col1, g_col1);
    cudaGetSymbolAddress((void**)&col2, g_col2);
    cudaGetSymbolAddress((void**)&p1,   g_part1);
    cudaGetSymbolAddress((void**)&p2,   g_part2);

    static bool attr_done = false;
    if (!attr_done) {
        cudaFuncSetAttribute(gemm_scale_kernel,
                             cudaFuncAttributeMaxDynamicSharedMemorySize, GEMM_SMEM);
        attr_done = true;
    }

    float* out_z = (float*)d_out;
    float* out_x = (float*)d_out + (long)NN * D;

    // ---- CSR build ----
    int nedge2 = (E1 >> 1) + (E2 >> 1) + 2;
    zero_both_kernel<<<(2 * NN + 255) / 256, 256>>>(cnt1, cnt2);
    count_both_kernel<<<(nedge2 + 255) / 256, 256>>>(ei1, E1, ei2, E2, cnt1, cnt2);
    partial_dinv_kernel<<<2 * NPART, 256>>>(cnt1, dinv1, p1, cnt2, dinv2, p2);
    scan_partials_kernel<<<2, 64>>>(p1, rp1, p2, rp2);
    scan_tiles_kernel<<<2 * NPART, 1024>>>(cnt1, rp1, cur1, p1, cnt2, rp2, cur2, p2);
    fill_both_kernel<<<(nedge2 + 255) / 256, 256>>>(ei1, E1, cur1, col1,
                                                    ei2, E2, cur2, col2);

    const int gemm_blocks = (NN + 63) / 64;
    const int gat_blocks  = (NN * 32 + 255) / 256;

    auto layer = [&](const float* A, const float* Wt, const float* bt,
                     const int* rp, const int* col, const float* dinv,
                     float* o, int relu) {
        gemm_scale_kernel<<<gemm_blocks, 128, GEMM_SMEM>>>(A, Wt, dinv, gp, NN);
        gather_finalize_kernel<<<gat_blocks, 256>>>(
            (const float4*)gp, rp, col, dinv, (const float4*)bt,
            (float4*)o, relu);
    };

    layer(x,     W1, b1, rp1, col1, dinv1, actp,  0);  // h  = elu(conv1)
    layer(actp,  W2, b2, rp2, col2, dinv2, out_z, 0);  // z  = elu(conv2)
    layer(out_z, W3, b3, rp1, col1, dinv1, actp,  0);  // h  = elu(conv3)
    layer(actp,  W4, b4, rp2, col2, dinv2, out_x, 1);  // xr = relu(conv4)
}